// round 2
// baseline (speedup 1.0000x reference)
#include <cuda_runtime.h>
#include <cstdint>

// Problem constants: B=4, S=4096, C=2048, O=2048, H=8, DH=256
#define M_TOT 16384      // B*S
#define CDIM  2048
#define ODIM  2048
#define NHEAD 8
#define DHEAD 256
#define LN_EPS 1e-5f

// ---------------- scratch (device globals; no allocation allowed) ----------
__device__ float g_q[(size_t)M_TOT * ODIM];     // later reused as y = x + out
__device__ float g_k[(size_t)M_TOT * ODIM];
__device__ float g_v[(size_t)M_TOT * ODIM];
__device__ float g_att[(size_t)M_TOT * ODIM];

// ---------------- GEMM: 128x128x32 tile, mma.sync m16n8k8 tf32 -------------
#define BM 128
#define BN 128
#define BK 32
#define SAS (BK + 4)     // 36 words  -> A-fragment LDS conflict-free (4m+k)
#define SBS (BN + 8)     // 136 words -> B-fragment LDS conflict-free (8k+n)

__device__ __forceinline__ uint32_t f2tf(float f) {
    uint32_t r;
    asm("cvt.rna.tf32.f32 %0, %1;" : "=r"(r) : "f"(f));
    return r;
}

__device__ __forceinline__ void mma8(float* c, const uint32_t* a, const uint32_t* b) {
    asm volatile(
        "mma.sync.aligned.m16n8k8.row.col.f32.tf32.tf32.f32 "
        "{%0,%1,%2,%3},{%4,%5,%6,%7},{%8,%9},{%0,%1,%2,%3};"
        : "+f"(c[0]), "+f"(c[1]), "+f"(c[2]), "+f"(c[3])
        : "r"(a[0]), "r"(a[1]), "r"(a[2]), "r"(a[3]), "r"(b[0]), "r"(b[1]));
}

// out[m][n] = sum_k A[m][k] * W[k][n] + bias[n] (+ resid[m][n])
// M = 16384, N = K = 2048, all row-major.
__device__ __forceinline__ void gemm_tile(
    const float* __restrict__ A, const float* __restrict__ W,
    const float* __restrict__ bias, const float* __restrict__ resid,
    float* __restrict__ out)
{
    __shared__ uint32_t sA[BM][SAS];
    __shared__ uint32_t sB[BK][SBS];

    const int K = CDIM, N = ODIM;
    const int tid  = threadIdx.x;
    const int bm   = blockIdx.y, bn = blockIdx.x;
    const int lane = tid & 31,   warp = tid >> 5;
    const int wm   = (warp & 1) * 64;      // 2 warps over M
    const int wn   = (warp >> 1) * 32;     // 4 warps over N
    const int g    = lane >> 2, tg = lane & 3;

    float acc[4][4][4];
#pragma unroll
    for (int i = 0; i < 4; i++)
#pragma unroll
        for (int j = 0; j < 4; j++)
#pragma unroll
            for (int r = 0; r < 4; r++) acc[i][j][r] = 0.f;

    // gmem load mapping (256 threads, 4 float4 each per tile)
    const int arow = tid >> 3;          // +32*i
    const int acol = (tid & 7) * 4;
    const int brow = tid >> 5;          // +8*i
    const int bcol = (tid & 31) * 4;
    const float* Ab = A + (size_t)(bm * BM) * K;
    const float* Wb = W + bn * BN;

    float4 ra[4], rb[4];

    auto LOAD = [&](int kt) {
#pragma unroll
        for (int i = 0; i < 4; i++) {
            ra[i] = *(const float4*)(Ab + (size_t)(arow + 32 * i) * K + kt * BK + acol);
            rb[i] = *(const float4*)(Wb + (size_t)(kt * BK + brow + 8 * i) * N + bcol);
        }
    };
    auto STORE = [&]() {
#pragma unroll
        for (int i = 0; i < 4; i++) {
            uint4 ta = make_uint4(f2tf(ra[i].x), f2tf(ra[i].y), f2tf(ra[i].z), f2tf(ra[i].w));
            *(uint4*)&sA[arow + 32 * i][acol] = ta;
            uint4 tb = make_uint4(f2tf(rb[i].x), f2tf(rb[i].y), f2tf(rb[i].z), f2tf(rb[i].w));
            *(uint4*)&sB[brow + 8 * i][bcol] = tb;
        }
    };
    auto COMPUTE = [&]() {
#pragma unroll
        for (int ks = 0; ks < 4; ks++) {
            uint32_t af[4][4], bf[4][2];
            const int k0 = ks * 8 + tg;
#pragma unroll
            for (int mi = 0; mi < 4; mi++) {
                const int m0 = wm + mi * 16 + g;
                af[mi][0] = sA[m0][k0];
                af[mi][1] = sA[m0 + 8][k0];
                af[mi][2] = sA[m0][k0 + 4];
                af[mi][3] = sA[m0 + 8][k0 + 4];
            }
#pragma unroll
            for (int ni = 0; ni < 4; ni++) {
                const int n0 = wn + ni * 8 + g;
                bf[ni][0] = sB[k0][n0];
                bf[ni][1] = sB[k0 + 4][n0];
            }
#pragma unroll
            for (int mi = 0; mi < 4; mi++)
#pragma unroll
                for (int ni = 0; ni < 4; ni++)
                    mma8(acc[mi][ni], af[mi], bf[ni]);
        }
    };

    LOAD(0);
    STORE();
    __syncthreads();
    const int NKT = K / BK;   // 64
    for (int kt = 0; kt < NKT; kt++) {
        const bool more = (kt + 1 < NKT);
        if (more) LOAD(kt + 1);
        COMPUTE();
        if (more) {
            __syncthreads();
            STORE();
            __syncthreads();
        }
    }

    // epilogue
#pragma unroll
    for (int mi = 0; mi < 4; mi++) {
        const int m0 = bm * BM + wm + mi * 16 + g;
#pragma unroll
        for (int ni = 0; ni < 4; ni++) {
            const int n0 = bn * BN + wn + ni * 8 + tg * 2;
            const float b0 = bias[n0], b1 = bias[n0 + 1];
            const size_t o0 = (size_t)m0 * N + n0;
            const size_t o1 = (size_t)(m0 + 8) * N + n0;
            float r00 = 0.f, r01 = 0.f, r10 = 0.f, r11 = 0.f;
            if (resid) {
                r00 = resid[o0]; r01 = resid[o0 + 1];
                r10 = resid[o1]; r11 = resid[o1 + 1];
            }
            out[o0]     = acc[mi][ni][0] + b0 + r00;
            out[o0 + 1] = acc[mi][ni][1] + b1 + r01;
            out[o1]     = acc[mi][ni][2] + b0 + r10;
            out[o1 + 1] = acc[mi][ni][3] + b1 + r11;
        }
    }
}

__global__ void __launch_bounds__(256, 1) qkv_kernel(
    const float* __restrict__ x,
    const float* __restrict__ Wq, const float* __restrict__ bq,
    const float* __restrict__ Wk, const float* __restrict__ bk,
    const float* __restrict__ Wv, const float* __restrict__ bv)
{
    const int z = blockIdx.z;
    const float* W = (z == 0) ? Wq : ((z == 1) ? Wk : Wv);
    const float* b = (z == 0) ? bq : ((z == 1) ? bk : bv);
    float* o       = (z == 0) ? g_q : ((z == 1) ? g_k : g_v);
    gemm_tile(x, W, b, nullptr, o);
}

__global__ void __launch_bounds__(256, 1) oproj_kernel(
    const float* __restrict__ x, const float* __restrict__ Wo,
    const float* __restrict__ bo)
{
    // y = attended @ Wo + bo + x  -> stored into g_q (q no longer needed)
    gemm_tile(g_att, Wo, bo, x, g_q);
}

// ---------------- per-position 8x8 head attention ---------------------------
// scores[h][t] = q[h,:].k[t,:]/16 ; softmax over t ; att[h,:] = sum_t a*v[t,:]
__global__ void __launch_bounds__(256) attn_kernel()
{
    __shared__ float sq[ODIM], sk[ODIM], sv[ODIM];
    const int p   = blockIdx.x;
    const int tid = threadIdx.x;
    const float4* q4 = (const float4*)(g_q + (size_t)p * ODIM);
    const float4* k4 = (const float4*)(g_k + (size_t)p * ODIM);
    const float4* v4 = (const float4*)(g_v + (size_t)p * ODIM);
#pragma unroll
    for (int i = tid; i < ODIM / 4; i += 256) {
        ((float4*)sq)[i] = q4[i];
        ((float4*)sk)[i] = k4[i];
        ((float4*)sv)[i] = v4[i];
    }
    __syncthreads();

    const int h = tid >> 5, lane = tid & 31;
    float s[NHEAD];
#pragma unroll
    for (int t = 0; t < NHEAD; t++) {
        float part = 0.f;
#pragma unroll
        for (int j = 0; j < 8; j++) {
            const int d = lane + 32 * j;
            part += sq[h * DHEAD + d] * sk[t * DHEAD + d];
        }
#pragma unroll
        for (int off = 16; off > 0; off >>= 1)
            part += __shfl_xor_sync(0xffffffffu, part, off);
        s[t] = part * 0.0625f;   // 1/sqrt(256)
    }
    float mx = s[0];
#pragma unroll
    for (int t = 1; t < NHEAD; t++) mx = fmaxf(mx, s[t]);
    float sum = 0.f;
#pragma unroll
    for (int t = 0; t < NHEAD; t++) { s[t] = __expf(s[t] - mx); sum += s[t]; }
    const float inv = 1.f / sum;

    float* ao = g_att + (size_t)p * ODIM + h * DHEAD;
#pragma unroll
    for (int j = 0; j < 8; j++) {
        const int d = lane + 32 * j;
        float o = 0.f;
#pragma unroll
        for (int t = 0; t < NHEAD; t++) o += s[t] * sv[t * DHEAD + d];
        ao[d] = o * inv;
    }
}

// ---------------- LayerNorm over channel dim --------------------------------
__global__ void __launch_bounds__(256) ln_kernel(
    const float* __restrict__ gamma, const float* __restrict__ beta,
    float* __restrict__ out)
{
    const int row = blockIdx.x;
    const int tid = threadIdx.x;
    const float4* y4 = (const float4*)(g_q + (size_t)row * CDIM);
    const float4 v0 = y4[tid];
    const float4 v1 = y4[tid + 256];
    float s = v0.x + v0.y + v0.z + v0.w + v1.x + v1.y + v1.z + v1.w;
    float q = v0.x * v0.x + v0.y * v0.y + v0.z * v0.z + v0.w * v0.w +
              v1.x * v1.x + v1.y * v1.y + v1.z * v1.z + v1.w * v1.w;
#pragma unroll
    for (int off = 16; off > 0; off >>= 1) {
        s += __shfl_xor_sync(0xffffffffu, s, off);
        q += __shfl_xor_sync(0xffffffffu, q, off);
    }
    __shared__ float rs[8], rq[8];
    const int warp = tid >> 5, lane = tid & 31;
    if (lane == 0) { rs[warp] = s; rq[warp] = q; }
    __syncthreads();
    float S = 0.f, Q = 0.f;
#pragma unroll
    for (int i = 0; i < 8; i++) { S += rs[i]; Q += rq[i]; }
    const float mu   = S * (1.f / CDIM);
    const float var  = Q * (1.f / CDIM) - mu * mu;
    const float rstd = rsqrtf(var + LN_EPS);

    const float4* g4 = (const float4*)gamma;
    const float4* b4 = (const float4*)beta;
    float4* o4 = (float4*)(out + (size_t)row * CDIM);

    float4 ga = g4[tid], be = b4[tid], o;
    o.x = ga.x * (v0.x - mu) * rstd + be.x;
    o.y = ga.y * (v0.y - mu) * rstd + be.y;
    o.z = ga.z * (v0.z - mu) * rstd + be.z;
    o.w = ga.w * (v0.w - mu) * rstd + be.w;
    o4[tid] = o;
    ga = g4[tid + 256]; be = b4[tid + 256];
    o.x = ga.x * (v1.x - mu) * rstd + be.x;
    o.y = ga.y * (v1.y - mu) * rstd + be.y;
    o.z = ga.z * (v1.z - mu) * rstd + be.z;
    o.w = ga.w * (v1.w - mu) * rstd + be.w;
    o4[tid + 256] = o;
}

// ---------------- launch ----------------------------------------------------
extern "C" void kernel_launch(void* const* d_in, const int* in_sizes, int n_in,
                              void* d_out, int out_size)
{
    const float* x     = (const float*)d_in[0];
    const float* Wq    = (const float*)d_in[1];
    const float* bq    = (const float*)d_in[2];
    const float* Wk    = (const float*)d_in[3];
    const float* bk    = (const float*)d_in[4];
    const float* Wv    = (const float*)d_in[5];
    const float* bv    = (const float*)d_in[6];
    const float* Wo    = (const float*)d_in[7];
    const float* bo    = (const float*)d_in[8];
    const float* gamma = (const float*)d_in[9];
    const float* beta  = (const float*)d_in[10];
    float* out = (float*)d_out;

    dim3 blk(256);
    dim3 gqkv(ODIM / BN, M_TOT / BM, 3);
    qkv_kernel<<<gqkv, blk>>>(x, Wq, bq, Wk, bk, Wv, bv);
    attn_kernel<<<M_TOT, blk>>>();
    dim3 go(CDIM / BN, M_TOT / BM);
    oproj_kernel<<<go, blk>>>(x, Wo, bo);
    ln_kernel<<<M_TOT, blk>>>(gamma, beta, out);
}

// round 4
// speedup vs baseline: 1.1008x; 1.1008x over previous
#include <cuda_runtime.h>
#include <cstdint>

// Problem: B=4, S=4096, C=O=2048, H=8, DH=256
#define MT    16384
#define KD    2048
#define ND    2048
#define NHEAD 8
#define DHEAD 256
#define LN_EPS 1e-5f

// ---------------- GEMM tiling ------------------------------------------------
#define BM 128
#define BN 128
#define BK 32
#define NKT (KD / BK)          // 64
#define STAGES 4
#define SAS 36                 // A row stride in words (32 + 4 pad)
#define SBS 136                // B row stride in words (128 + 8 pad)
#define A_STAGE_B (BM * SAS * 4)          // 18432
#define B_STAGE_B (BK * SBS * 4)          // 17408
#define STAGE_B   (A_STAGE_B + B_STAGE_B) // 35840
#define SMEM_TOTAL (STAGES * STAGE_B)     // 143360

// ---------------- scratch ----------------------------------------------------
__device__ float g_xr[(size_t)MT * KD];       // x rounded to tf32
__device__ float g_w[4][(size_t)KD * ND];     // Wq,Wk,Wv,Wo rounded ([k][n])
__device__ float g_q[(size_t)MT * ND];        // Q, later reused as y
__device__ float g_k[(size_t)MT * ND];
__device__ float g_v[(size_t)MT * ND];
__device__ float g_att[(size_t)MT * ND];      // attended (tf32-rounded)

// ---------------- helpers ----------------------------------------------------
__device__ __forceinline__ uint32_t smem_u32(const void* p) {
    uint32_t a;
    asm("{ .reg .u64 t; cvta.to.shared.u64 t, %1; cvt.u32.u64 %0, t; }"
        : "=r"(a) : "l"(p));
    return a;
}
__device__ __forceinline__ uint32_t f2tf(float f) {
    uint32_t r;
    asm("cvt.rna.tf32.f32 %0, %1;" : "=r"(r) : "f"(f));
    return r;
}
__device__ __forceinline__ float rna(float f) { return __uint_as_float(f2tf(f)); }

__device__ __forceinline__ void cpa16(uint32_t dst, const float* src) {
    asm volatile("cp.async.cg.shared.global [%0], [%1], 16;" :: "r"(dst), "l"(src));
}
__device__ __forceinline__ void mma8(float* c, const uint32_t* a, const uint32_t* b) {
    asm volatile(
        "mma.sync.aligned.m16n8k8.row.col.f32.tf32.tf32.f32 "
        "{%0,%1,%2,%3},{%4,%5,%6,%7},{%8,%9},{%0,%1,%2,%3};"
        : "+f"(c[0]), "+f"(c[1]), "+f"(c[2]), "+f"(c[3])
        : "r"(a[0]), "r"(a[1]), "r"(a[2]), "r"(a[3]), "r"(b[0]), "r"(b[1]));
}

// ---------------- GEMM core --------------------------------------------------
// out[m][n] = sum_k A[m][k] * W[k][n] + bias[n] (+ resid[m][n])
// A: [MT][KD] (tf32-rounded), W: [KD][ND] (tf32-rounded), row-major.
__device__ __forceinline__ void gemm_core(
    const float* __restrict__ A, const float* __restrict__ W,
    const float* __restrict__ bias, const float* __restrict__ resid,
    float* __restrict__ out, int m0, int n0)
{
    extern __shared__ char smem[];
    const uint32_t sb = smem_u32(smem);
    const int tid  = threadIdx.x;
    const int lane = tid & 31, warp = tid >> 5;
    const int wm   = (warp & 1) * 64;      // 2 warps over M
    const int wn   = (warp >> 1) * 32;     // 4 warps over N
    const int g    = lane >> 2, tg = lane & 3;

    float acc[4][4][4];
#pragma unroll
    for (int i = 0; i < 4; i++)
#pragma unroll
        for (int j = 0; j < 4; j++)
#pragma unroll
            for (int r = 0; r < 4; r++) acc[i][j][r] = 0.f;

    const float* Ab = A + (size_t)m0 * KD;
    const float* Wb = W + n0;

    // per-thread: 4 A chunks + 4 B chunks (16B each), chunk id = i*256 + tid
    auto load_stage = [&](int kt, int s) {
        const uint32_t baseA = sb + s * STAGE_B;
        const uint32_t baseB = baseA + A_STAGE_B;
#pragma unroll
        for (int i = 0; i < 4; i++) {
            const int ca = i * 256 + tid;
            const int ar = ca >> 3, ac = ca & 7;          // row 0..127, chunk 0..7
            cpa16(baseA + ar * (SAS * 4) + ac * 16,
                  Ab + (size_t)ar * KD + kt * BK + ac * 4);
            const int cb = i * 256 + tid;
            const int br = cb >> 5, bc = cb & 31;         // row 0..31, chunk 0..31
            cpa16(baseB + br * (SBS * 4) + bc * 16,
                  Wb + (size_t)(kt * BK + br) * ND + bc * 4);
        }
    };

#pragma unroll
    for (int kt = 0; kt < STAGES - 1; kt++) {
        load_stage(kt, kt);
        asm volatile("cp.async.commit_group;" ::: "memory");
    }

#pragma unroll 1
    for (int kt = 0; kt < NKT; kt++) {
        asm volatile("cp.async.wait_group 2;" ::: "memory");
        __syncthreads();
        if (kt + STAGES - 1 < NKT)
            load_stage(kt + STAGES - 1, (kt + STAGES - 1) & (STAGES - 1));
        asm volatile("cp.async.commit_group;" ::: "memory");

        const int s = kt & (STAGES - 1);
        const uint32_t* sA = (const uint32_t*)(smem + s * STAGE_B);
        const uint32_t* sBm = (const uint32_t*)(smem + s * STAGE_B + A_STAGE_B);
#pragma unroll
        for (int ks = 0; ks < 4; ks++) {
            uint32_t af[4][4], bf[4][2];
            const int k0 = ks * 8 + tg;
#pragma unroll
            for (int mi = 0; mi < 4; mi++) {
                const int mrow = wm + mi * 16 + g;
                af[mi][0] = sA[mrow * SAS + k0];
                af[mi][1] = sA[(mrow + 8) * SAS + k0];
                af[mi][2] = sA[mrow * SAS + k0 + 4];
                af[mi][3] = sA[(mrow + 8) * SAS + k0 + 4];
            }
#pragma unroll
            for (int ni = 0; ni < 4; ni++) {
                const int ncol = wn + ni * 8 + g;
                bf[ni][0] = sBm[k0 * SBS + ncol];
                bf[ni][1] = sBm[(k0 + 4) * SBS + ncol];
            }
#pragma unroll
            for (int mi = 0; mi < 4; mi++)
#pragma unroll
                for (int ni = 0; ni < 4; ni++)
                    mma8(acc[mi][ni], af[mi], bf[ni]);
        }
    }

    // epilogue (direct from accumulators)
#pragma unroll
    for (int mi = 0; mi < 4; mi++) {
        const int m = m0 + wm + mi * 16 + g;
#pragma unroll
        for (int ni = 0; ni < 4; ni++) {
            const int n = n0 + wn + ni * 8 + tg * 2;
            const float b0 = bias[n], b1 = bias[n + 1];
            const size_t o0 = (size_t)m * ND + n;
            const size_t o1 = (size_t)(m + 8) * ND + n;
            float r00 = 0.f, r01 = 0.f, r10 = 0.f, r11 = 0.f;
            if (resid) {
                r00 = resid[o0]; r01 = resid[o0 + 1];
                r10 = resid[o1]; r11 = resid[o1 + 1];
            }
            out[o0]     = acc[mi][ni][0] + b0 + r00;
            out[o0 + 1] = acc[mi][ni][1] + b1 + r01;
            out[o1]     = acc[mi][ni][2] + b0 + r10;
            out[o1 + 1] = acc[mi][ni][3] + b1 + r11;
        }
    }
}

__global__ void __launch_bounds__(256, 1) gemm_qkv_kernel(
    const float* __restrict__ bq, const float* __restrict__ bk,
    const float* __restrict__ bv)
{
    const int z  = blockIdx.x >> 4;          // bn fastest -> weights L2-resident
    const int bn = blockIdx.x & 15;
    const float* bias = (z == 0) ? bq : ((z == 1) ? bk : bv);
    float* out        = (z == 0) ? g_q : ((z == 1) ? g_k : g_v);
    gemm_core(g_xr, g_w[z], bias, nullptr, out, blockIdx.y * BM, bn * BN);
}

__global__ void __launch_bounds__(256, 1) gemm_o_kernel(
    const float* __restrict__ bo, const float* __restrict__ x)
{
    gemm_core(g_att, g_w[3], bo, x, g_q, blockIdx.y * BM, blockIdx.x * BN);
}

// ---------------- prep: RNA-round x and W in place ---------------------------
__global__ void __launch_bounds__(256) prep_x_kernel(const float* __restrict__ x)
{
    const size_t i = ((size_t)blockIdx.x * 256 + threadIdx.x) * 4;
    float4 v = *(const float4*)(x + i);
    v.x = rna(v.x); v.y = rna(v.y); v.z = rna(v.z); v.w = rna(v.w);
    *(float4*)(g_xr + i) = v;
}

__global__ void __launch_bounds__(256) prep_w_kernel(
    const float* __restrict__ Wq, const float* __restrict__ Wk,
    const float* __restrict__ Wv, const float* __restrict__ Wo)
{
    const int z = blockIdx.y;
    const float* W = (z == 0) ? Wq : ((z == 1) ? Wk : ((z == 2) ? Wv : Wo));
    const size_t i = ((size_t)blockIdx.x * 256 + threadIdx.x) * 4;
    float4 v = *(const float4*)(W + i);
    v.x = rna(v.x); v.y = rna(v.y); v.z = rna(v.z); v.w = rna(v.w);
    *(float4*)(g_w[z] + i) = v;
}

// ---------------- per-position 8x8 head attention ----------------------------
__global__ void __launch_bounds__(256) attn_kernel()
{
    __shared__ float sq[ND], sk[ND], sv[ND];
    const int p = blockIdx.x, tid = threadIdx.x;
    const float4* q4 = (const float4*)(g_q + (size_t)p * ND);
    const float4* k4 = (const float4*)(g_k + (size_t)p * ND);
    const float4* v4 = (const float4*)(g_v + (size_t)p * ND);
#pragma unroll
    for (int i = tid; i < ND / 4; i += 256) {
        ((float4*)sq)[i] = q4[i];
        ((float4*)sk)[i] = k4[i];
        ((float4*)sv)[i] = v4[i];
    }
    __syncthreads();

    const int h = tid >> 5, lane = tid & 31;
    float s[NHEAD];
#pragma unroll
    for (int t = 0; t < NHEAD; t++) {
        float part = 0.f;
#pragma unroll
        for (int j = 0; j < 8; j++) {
            const int d = lane + 32 * j;
            part += sq[h * DHEAD + d] * sk[t * DHEAD + d];
        }
#pragma unroll
        for (int off = 16; off > 0; off >>= 1)
            part += __shfl_xor_sync(0xffffffffu, part, off);
        s[t] = part * 0.0625f;     // 1/sqrt(256)
    }
    float mx = s[0];
#pragma unroll
    for (int t = 1; t < NHEAD; t++) mx = fmaxf(mx, s[t]);
    float sum = 0.f;
#pragma unroll
    for (int t = 0; t < NHEAD; t++) { s[t] = __expf(s[t] - mx); sum += s[t]; }
    const float inv = 1.f / sum;

    float* ao = g_att + (size_t)p * ND + h * DHEAD;
#pragma unroll
    for (int j = 0; j < 8; j++) {
        const int d = lane + 32 * j;
        float o = 0.f;
#pragma unroll
        for (int t = 0; t < NHEAD; t++) o += s[t] * sv[t * DHEAD + d];
        ao[d] = rna(o * inv);      // tf32-rounded: O-proj GEMM input
    }
}

// ---------------- LayerNorm --------------------------------------------------
__global__ void __launch_bounds__(256) ln_kernel(
    const float* __restrict__ gamma, const float* __restrict__ beta,
    float* __restrict__ out)
{
    const int row = blockIdx.x, tid = threadIdx.x;
    const float4* y4 = (const float4*)(g_q + (size_t)row * KD);
    const float4 v0 = y4[tid];
    const float4 v1 = y4[tid + 256];
    float s = v0.x + v0.y + v0.z + v0.w + v1.x + v1.y + v1.z + v1.w;
    float q = v0.x * v0.x + v0.y * v0.y + v0.z * v0.z + v0.w * v0.w +
              v1.x * v1.x + v1.y * v1.y + v1.z * v1.z + v1.w * v1.w;
#pragma unroll
    for (int off = 16; off > 0; off >>= 1) {
        s += __shfl_xor_sync(0xffffffffu, s, off);
        q += __shfl_xor_sync(0xffffffffu, q, off);
    }
    __shared__ float rs[8], rq[8];
    const int warp = tid >> 5, lane = tid & 31;
    if (lane == 0) { rs[warp] = s; rq[warp] = q; }
    __syncthreads();
    float S = 0.f, Q = 0.f;
#pragma unroll
    for (int i = 0; i < 8; i++) { S += rs[i]; Q += rq[i]; }
    const float mu   = S * (1.f / KD);
    const float var  = Q * (1.f / KD) - mu * mu;
    const float rstd = rsqrtf(var + LN_EPS);

    const float4* g4 = (const float4*)gamma;
    const float4* b4 = (const float4*)beta;
    float4* o4 = (float4*)(out + (size_t)row * KD);

    float4 ga = g4[tid], be = b4[tid], o;
    o.x = ga.x * (v0.x - mu) * rstd + be.x;
    o.y = ga.y * (v0.y - mu) * rstd + be.y;
    o.z = ga.z * (v0.z - mu) * rstd + be.z;
    o.w = ga.w * (v0.w - mu) * rstd + be.w;
    o4[tid] = o;
    ga = g4[tid + 256]; be = b4[tid + 256];
    o.x = ga.x * (v1.x - mu) * rstd + be.x;
    o.y = ga.y * (v1.y - mu) * rstd + be.y;
    o.z = ga.z * (v1.z - mu) * rstd + be.z;
    o.w = ga.w * (v1.w - mu) * rstd + be.w;
    o4[tid + 256] = o;
}

// ---------------- launch -----------------------------------------------------
extern "C" void kernel_launch(void* const* d_in, const int* in_sizes, int n_in,
                              void* d_out, int out_size)
{
    const float* x     = (const float*)d_in[0];
    const float* Wq    = (const float*)d_in[1];
    const float* bq    = (const float*)d_in[2];
    const float* Wk    = (const float*)d_in[3];
    const float* bk    = (const float*)d_in[4];
    const float* Wv    = (const float*)d_in[5];
    const float* bv    = (const float*)d_in[6];
    const float* Wo    = (const float*)d_in[7];
    const float* bo    = (const float*)d_in[8];
    const float* gamma = (const float*)d_in[9];
    const float* beta  = (const float*)d_in[10];
    float* out = (float*)d_out;

    cudaFuncSetAttribute(gemm_qkv_kernel,
                         cudaFuncAttributeMaxDynamicSharedMemorySize, SMEM_TOTAL);
    cudaFuncSetAttribute(gemm_o_kernel,
                         cudaFuncAttributeMaxDynamicSharedMemorySize, SMEM_TOTAL);

    prep_x_kernel<<<(MT * (size_t)KD) / 1024, 256>>>(x);
    prep_w_kernel<<<dim3((KD * (size_t)ND) / 1024, 4), 256>>>(Wq, Wk, Wv, Wo);
    gemm_qkv_kernel<<<dim3(48, MT / BM), 256, SMEM_TOTAL>>>(bq, bk, bv);
    attn_kernel<<<MT, 256>>>();
    gemm_o_kernel<<<dim3(ND / BN, MT / BM), 256, SMEM_TOTAL>>>(bo, x);
    ln_kernel<<<MT, 256>>>(gamma, beta, out);
}

// round 6
// speedup vs baseline: 1.2795x; 1.1624x over previous
#include <cuda_runtime.h>
#include <cstdint>

// Problem: B=4, S=4096, C=O=2048, H=8, DH=256
#define MT    16384
#define KD    2048
#define ND    2048
#define NHEAD 8
#define DHEAD 256
#define LN_EPS 1e-5f

// ---------------- GEMM tiling ------------------------------------------------
#define BM 128
#define BN 128
#define BK 32
#define NKT (KD / BK)          // 64
#define STAGES 3
#define SAS 36                 // A row stride in words (32 + 4 pad)
#define SBS 136                // B row stride in words (128 + 8 pad)
#define A_STAGE_B (BM * SAS * 4)          // 18432
#define B_STAGE_B (BK * SBS * 4)          // 17408
#define STAGE_B   (A_STAGE_B + B_STAGE_B) // 35840
#define SMEM_TOTAL (STAGES * STAGE_B)     // 107520 -> 2 CTAs/SM

// ---------------- scratch ----------------------------------------------------
__device__ float g_xr[(size_t)MT * KD];       // x rounded to tf32
__device__ float g_w[4][(size_t)KD * ND];     // Wq,Wk,Wv,Wo rounded ([k][n])
__device__ float g_q[(size_t)MT * ND];        // Q, later reused as y
__device__ float g_k[(size_t)MT * ND];
__device__ float g_v[(size_t)MT * ND];
__device__ float g_att[(size_t)MT * ND];      // attended (tf32-rounded)

// ---------------- helpers ----------------------------------------------------
__device__ __forceinline__ uint32_t smem_u32(const void* p) {
    uint32_t a;
    asm("{ .reg .u64 t; cvta.to.shared.u64 t, %1; cvt.u32.u64 %0, t; }"
        : "=r"(a) : "l"(p));
    return a;
}
__device__ __forceinline__ uint32_t f2tf(float f) {
    uint32_t r;
    asm("cvt.rna.tf32.f32 %0, %1;" : "=r"(r) : "f"(f));
    return r;
}
__device__ __forceinline__ float rna(float f) { return __uint_as_float(f2tf(f)); }

__device__ __forceinline__ void cpa16(uint32_t dst, const float* src) {
    asm volatile("cp.async.cg.shared.global [%0], [%1], 16;" :: "r"(dst), "l"(src));
}
__device__ __forceinline__ void mma8(float* c, const uint32_t* a, const uint32_t* b) {
    asm volatile(
        "mma.sync.aligned.m16n8k8.row.col.f32.tf32.tf32.f32 "
        "{%0,%1,%2,%3},{%4,%5,%6,%7},{%8,%9},{%0,%1,%2,%3};"
        : "+f"(c[0]), "+f"(c[1]), "+f"(c[2]), "+f"(c[3])
        : "r"(a[0]), "r"(a[1]), "r"(a[2]), "r"(a[3]), "r"(b[0]), "r"(b[1]));
}

// ---------------- GEMM core --------------------------------------------------
// out[m][n] = sum_k A[m][k] * W[k][n] + bias[n] (+ resid[m][n])
// A: [MT][KD] (tf32-rounded), W: [KD][ND] (tf32-rounded), row-major.
__device__ __forceinline__ void gemm_core(
    const float* __restrict__ A, const float* __restrict__ W,
    const float* __restrict__ bias, const float* __restrict__ resid,
    float* __restrict__ out, int m0, int n0)
{
    extern __shared__ char smem[];
    const uint32_t sb = smem_u32(smem);
    const int tid  = threadIdx.x;
    const int lane = tid & 31, warp = tid >> 5;
    const int wm   = (warp & 1) * 64;      // 2 warps over M
    const int wn   = (warp >> 1) * 32;     // 4 warps over N
    const int g    = lane >> 2, tg = lane & 3;

    float acc[4][4][4];
#pragma unroll
    for (int i = 0; i < 4; i++)
#pragma unroll
        for (int j = 0; j < 4; j++)
#pragma unroll
            for (int r = 0; r < 4; r++) acc[i][j][r] = 0.f;

    const float* Ab = A + (size_t)m0 * KD;
    const float* Wb = W + n0;

    // per-thread: 4 A chunks + 4 B chunks (16B each), chunk id = i*256 + tid
    auto load_stage = [&](int kt, int s) {
        const uint32_t baseA = sb + s * STAGE_B;
        const uint32_t baseB = baseA + A_STAGE_B;
#pragma unroll
        for (int i = 0; i < 4; i++) {
            const int ca = i * 256 + tid;
            const int ar = ca >> 3, ac = ca & 7;          // row 0..127, chunk 0..7
            cpa16(baseA + ar * (SAS * 4) + ac * 16,
                  Ab + (size_t)ar * KD + kt * BK + ac * 4);
            const int cb = i * 256 + tid;
            const int br = cb >> 5, bc = cb & 31;         // row 0..31, chunk 0..31
            cpa16(baseB + br * (SBS * 4) + bc * 16,
                  Wb + (size_t)(kt * BK + br) * ND + bc * 4);
        }
    };

    load_stage(0, 0);
    asm volatile("cp.async.commit_group;" ::: "memory");
    load_stage(1, 1);
    asm volatile("cp.async.commit_group;" ::: "memory");

    int sc = 0, sl = 2;
#pragma unroll 1
    for (int kt = 0; kt < NKT; kt++) {
        asm volatile("cp.async.wait_group 1;" ::: "memory");
        __syncthreads();
        if (kt + 2 < NKT) load_stage(kt + 2, sl);
        asm volatile("cp.async.commit_group;" ::: "memory");

        const uint32_t* sA  = (const uint32_t*)(smem + sc * STAGE_B);
        const uint32_t* sBm = (const uint32_t*)(smem + sc * STAGE_B + A_STAGE_B);
#pragma unroll
        for (int ks = 0; ks < 4; ks++) {
            uint32_t af[4][4], bf[4][2];
            const int k0 = ks * 8 + tg;
#pragma unroll
            for (int mi = 0; mi < 4; mi++) {
                const int mrow = wm + mi * 16 + g;
                af[mi][0] = sA[mrow * SAS + k0];
                af[mi][1] = sA[(mrow + 8) * SAS + k0];
                af[mi][2] = sA[mrow * SAS + k0 + 4];
                af[mi][3] = sA[(mrow + 8) * SAS + k0 + 4];
            }
#pragma unroll
            for (int ni = 0; ni < 4; ni++) {
                const int ncol = wn + ni * 8 + g;
                bf[ni][0] = sBm[k0 * SBS + ncol];
                bf[ni][1] = sBm[(k0 + 4) * SBS + ncol];
            }
#pragma unroll
            for (int mi = 0; mi < 4; mi++)
#pragma unroll
                for (int ni = 0; ni < 4; ni++)
                    mma8(acc[mi][ni], af[mi], bf[ni]);
        }
        sc = (sc == 2) ? 0 : sc + 1;
        sl = (sl == 2) ? 0 : sl + 1;
    }

    // epilogue (direct from accumulators)
#pragma unroll
    for (int mi = 0; mi < 4; mi++) {
        const int m = m0 + wm + mi * 16 + g;
#pragma unroll
        for (int ni = 0; ni < 4; ni++) {
            const int n = n0 + wn + ni * 8 + tg * 2;
            const float b0 = bias[n], b1 = bias[n + 1];
            const size_t o0 = (size_t)m * ND + n;
            const size_t o1 = (size_t)(m + 8) * ND + n;
            float r00 = 0.f, r01 = 0.f, r10 = 0.f, r11 = 0.f;
            if (resid) {
                r00 = resid[o0]; r01 = resid[o0 + 1];
                r10 = resid[o1]; r11 = resid[o1 + 1];
            }
            out[o0]     = acc[mi][ni][0] + b0 + r00;
            out[o0 + 1] = acc[mi][ni][1] + b1 + r01;
            out[o1]     = acc[mi][ni][2] + b0 + r10;
            out[o1 + 1] = acc[mi][ni][3] + b1 + r11;
        }
    }
}

__global__ void __launch_bounds__(256, 2) gemm_qkv_kernel(
    const float* __restrict__ bq, const float* __restrict__ bk,
    const float* __restrict__ bv)
{
    const int z  = blockIdx.x >> 4;          // bn fastest -> weights L2-resident
    const int bn = blockIdx.x & 15;
    const float* bias = (z == 0) ? bq : ((z == 1) ? bk : bv);
    float* out        = (z == 0) ? g_q : ((z == 1) ? g_k : g_v);
    gemm_core(g_xr, g_w[z], bias, nullptr, out, blockIdx.y * BM, bn * BN);
}

__global__ void __launch_bounds__(256, 2) gemm_o_kernel(
    const float* __restrict__ bo, const float* __restrict__ x)
{
    gemm_core(g_att, g_w[3], bo, x, g_q, blockIdx.y * BM, blockIdx.x * BN);
}

// ---------------- prep: RNA-round x and W in place ---------------------------
__global__ void __launch_bounds__(256) prep_x_kernel(const float* __restrict__ x)
{
    const size_t i = ((size_t)blockIdx.x * 256 + threadIdx.x) * 4;
    float4 v = *(const float4*)(x + i);
    v.x = rna(v.x); v.y = rna(v.y); v.z = rna(v.z); v.w = rna(v.w);
    *(float4*)(g_xr + i) = v;
}

__global__ void __launch_bounds__(256) prep_w_kernel(
    const float* __restrict__ Wq, const float* __restrict__ Wk,
    const float* __restrict__ Wv, const float* __restrict__ Wo)
{
    const int z = blockIdx.y;
    const float* W = (z == 0) ? Wq : ((z == 1) ? Wk : ((z == 2) ? Wv : Wo));
    const size_t i = ((size_t)blockIdx.x * 256 + threadIdx.x) * 4;
    float4 v = *(const float4*)(W + i);
    v.x = rna(v.x); v.y = rna(v.y); v.z = rna(v.z); v.w = rna(v.w);
    *(float4*)(g_w[z] + i) = v;
}

// ---------------- per-position 8x8 head attention ----------------------------
__global__ void __launch_bounds__(256) attn_kernel()
{
    __shared__ float sq[ND], sk[ND], sv[ND];
    const int p = blockIdx.x, tid = threadIdx.x;
    const float4* q4 = (const float4*)(g_q + (size_t)p * ND);
    const float4* k4 = (const float4*)(g_k + (size_t)p * ND);
    const float4* v4 = (const float4*)(g_v + (size_t)p * ND);
#pragma unroll
    for (int i = tid; i < ND / 4; i += 256) {
        ((float4*)sq)[i] = q4[i];
        ((float4*)sk)[i] = k4[i];
        ((float4*)sv)[i] = v4[i];
    }
    __syncthreads();

    const int h = tid >> 5, lane = tid & 31;
    float s[NHEAD];
#pragma unroll
    for (int t = 0; t < NHEAD; t++) {
        float part = 0.f;
#pragma unroll
        for (int j = 0; j < 8; j++) {
            const int d = lane + 32 * j;
            part += sq[h * DHEAD + d] * sk[t * DHEAD + d];
        }
#pragma unroll
        for (int off = 16; off > 0; off >>= 1)
            part += __shfl_xor_sync(0xffffffffu, part, off);
        s[t] = part * 0.0625f;     // 1/sqrt(256)
    }
    float mx = s[0];
#pragma unroll
    for (int t = 1; t < NHEAD; t++) mx = fmaxf(mx, s[t]);
    float sum = 0.f;
#pragma unroll
    for (int t = 0; t < NHEAD; t++) { s[t] = __expf(s[t] - mx); sum += s[t]; }
    const float inv = 1.f / sum;

    float* ao = g_att + (size_t)p * ND + h * DHEAD;
#pragma unroll
    for (int j = 0; j < 8; j++) {
        const int d = lane + 32 * j;
        float o = 0.f;
#pragma unroll
        for (int t = 0; t < NHEAD; t++) o += s[t] * sv[t * DHEAD + d];
        ao[d] = rna(o * inv);      // tf32-rounded: O-proj GEMM input
    }
}

// ---------------- LayerNorm --------------------------------------------------
__global__ void __launch_bounds__(256) ln_kernel(
    const float* __restrict__ gamma, const float* __restrict__ beta,
    float* __restrict__ out)
{
    const int row = blockIdx.x, tid = threadIdx.x;
    const float4* y4 = (const float4*)(g_q + (size_t)row * KD);
    const float4 v0 = y4[tid];
    const float4 v1 = y4[tid + 256];
    float s = v0.x + v0.y + v0.z + v0.w + v1.x + v1.y + v1.z + v1.w;
    float q = v0.x * v0.x + v0.y * v0.y + v0.z * v0.z + v0.w * v0.w +
              v1.x * v1.x + v1.y * v1.y + v1.z * v1.z + v1.w * v1.w;
#pragma unroll
    for (int off = 16; off > 0; off >>= 1) {
        s += __shfl_xor_sync(0xffffffffu, s, off);
        q += __shfl_xor_sync(0xffffffffu, q, off);
    }
    __shared__ float rs[8], rq[8];
    const int warp = tid >> 5, lane = tid & 31;
    if (lane == 0) { rs[warp] = s; rq[warp] = q; }
    __syncthreads();
    float S = 0.f, Q = 0.f;
#pragma unroll
    for (int i = 0; i < 8; i++) { S += rs[i]; Q += rq[i]; }
    const float mu   = S * (1.f / KD);
    const float var  = Q * (1.f / KD) - mu * mu;
    const float rstd = rsqrtf(var + LN_EPS);

    const float4* g4 = (const float4*)gamma;
    const float4* b4 = (const float4*)beta;
    float4* o4 = (float4*)(out + (size_t)row * KD);

    float4 ga = g4[tid], be = b4[tid], o;
    o.x = ga.x * (v0.x - mu) * rstd + be.x;
    o.y = ga.y * (v0.y - mu) * rstd + be.y;
    o.z = ga.z * (v0.z - mu) * rstd + be.z;
    o.w = ga.w * (v0.w - mu) * rstd + be.w;
    o4[tid] = o;
    ga = g4[tid + 256]; be = b4[tid + 256];
    o.x = ga.x * (v1.x - mu) * rstd + be.x;
    o.y = ga.y * (v1.y - mu) * rstd + be.y;
    o.z = ga.z * (v1.z - mu) * rstd + be.z;
    o.w = ga.w * (v1.w - mu) * rstd + be.w;
    o4[tid + 256] = o;
}

// ---------------- launch -----------------------------------------------------
extern "C" void kernel_launch(void* const* d_in, const int* in_sizes, int n_in,
                              void* d_out, int out_size)
{
    const float* x     = (const float*)d_in[0];
    const float* Wq    = (const float*)d_in[1];
    const float* bq    = (const float*)d_in[2];
    const float* Wk    = (const float*)d_in[3];
    const float* bk    = (const float*)d_in[4];
    const float* Wv    = (const float*)d_in[5];
    const float* bv    = (const float*)d_in[6];
    const float* Wo    = (const float*)d_in[7];
    const float* bo    = (const float*)d_in[8];
    const float* gamma = (const float*)d_in[9];
    const float* beta  = (const float*)d_in[10];
    float* out = (float*)d_out;

    cudaFuncSetAttribute(gemm_qkv_kernel,
                         cudaFuncAttributeMaxDynamicSharedMemorySize, SMEM_TOTAL);
    cudaFuncSetAttribute(gemm_o_kernel,
                         cudaFuncAttributeMaxDynamicSharedMemorySize, SMEM_TOTAL);

    prep_x_kernel<<<(MT * (size_t)KD) / 1024, 256>>>(x);
    prep_w_kernel<<<dim3((KD * (size_t)ND) / 1024, 4), 256>>>(Wq, Wk, Wv, Wo);
    gemm_qkv_kernel<<<dim3(48, MT / BM), 256, SMEM_TOTAL>>>(bq, bk, bv);
    attn_kernel<<<MT, 256>>>();
    gemm_o_kernel<<<dim3(ND / BN, MT / BM), 256, SMEM_TOTAL>>>(bo, x);
    ln_kernel<<<MT, 256>>>(gamma, beta, out);
}